// round 14
// baseline (speedup 1.0000x reference)
#include <cuda_runtime.h>
#include <cuda_fp16.h>
#include <math.h>

// Problem-fixed sizes: N=100000, E=1600000, D=128, EIG=32.
#define MAXN 100000
#define MAXE 1600000
#define FULLMASK 0xffffffffu
#define SCAN_BLOCKS 128
#define SCAN_THREADS 1024

// Scratch (device globals — explicitly zeroed by k_init every call).
__device__ float g_me[MAXN];
__device__ int   g_cnt[MAXN];
__device__ int   g_off[MAXN + 1];
__device__ float g_acc[3];
__device__ float g_par[2];          // [0]=exp(lambda0), [1]=c = gamma*sim
__device__ int2  g_edge[MAXE];      // (col, adj-as-int) sorted by row
__device__ uint2 g_vh[MAXN * 32];   // v fp16: lane layout, 4 halfs per uint2
__device__ uint4 g_kh4[MAXN * 16];  // k fp16: 8 halfs per uint4 (16-lane layout)
__device__ int   g_bsum[SCAN_BLOCKS];
__device__ int   g_bbase[SCAN_BLOCKS];

// ---- cache-policy-steered load helpers ----
__device__ __forceinline__ unsigned long long mk_policy_el() {
    unsigned long long pol;
    asm("createpolicy.fractional.L2::evict_last.b64 %0, 1.0;" : "=l"(pol));
    return pol;
}
__device__ __forceinline__ float2 ldg_el_f2(const float2* p,
                                            unsigned long long pol) {
    float2 r;
    asm("ld.global.nc.L2::cache_hint.v2.f32 {%0,%1},[%2],%3;"
        : "=f"(r.x), "=f"(r.y) : "l"(p), "l"(pol));
    return r;
}
__device__ __forceinline__ uint2 ldg_el_u2(const uint2* p,
                                           unsigned long long pol) {
    uint2 r;
    asm("ld.global.nc.L2::cache_hint.v2.u32 {%0,%1},[%2],%3;"
        : "=r"(r.x), "=r"(r.y) : "l"(p), "l"(pol));
    return r;
}
__device__ __forceinline__ uint4 ldg_el_u4(const uint4* p,
                                           unsigned long long pol) {
    uint4 r;
    asm("ld.global.nc.L2::cache_hint.v4.u32 {%0,%1,%2,%3},[%4],%5;"
        : "=r"(r.x), "=r"(r.y), "=r"(r.z), "=r"(r.w) : "l"(p), "l"(pol));
    return r;
}

// ---------------------------------------------------------------------------
__global__ void k_init(const float* __restrict__ memb,
                       const int* __restrict__ mids, int n) {
    int i = blockIdx.x * blockDim.x + threadIdx.x;
    if (i == 0) { g_acc[0] = 0.f; g_acc[1] = 0.f; g_acc[2] = 0.f; }
    if (i < n) {
        g_me[i]  = memb[__ldcs(&mids[i])];
        g_cnt[i] = 0;
    }
}

// ---------------------------------------------------------------------------
__global__ void k_pack(const float4* __restrict__ k4,
                       const float4* __restrict__ v4, int n) {
    int n16 = n * 16, n32 = n * 32;
    for (int i = blockIdx.x * blockDim.x + threadIdx.x; i < n16;
         i += gridDim.x * blockDim.x) {
        float4 a = __ldcs(&k4[2 * i]);
        float4 b = __ldcs(&k4[2 * i + 1]);
        __half2 h0 = __floats2half2_rn(a.x, a.y);
        __half2 h1 = __floats2half2_rn(a.z, a.w);
        __half2 h2 = __floats2half2_rn(b.x, b.y);
        __half2 h3 = __floats2half2_rn(b.z, b.w);
        uint4 u;
        u.x = *reinterpret_cast<unsigned*>(&h0);
        u.y = *reinterpret_cast<unsigned*>(&h1);
        u.z = *reinterpret_cast<unsigned*>(&h2);
        u.w = *reinterpret_cast<unsigned*>(&h3);
        g_kh4[i] = u;
    }
    for (int i = blockIdx.x * blockDim.x + threadIdx.x; i < n32;
         i += gridDim.x * blockDim.x) {
        float4 vv = __ldcs(&v4[i]);
        __half2 h0 = __floats2half2_rn(vv.x, vv.y);
        __half2 h1 = __floats2half2_rn(vv.z, vv.w);
        uint2 u;
        u.x = *reinterpret_cast<unsigned*>(&h0);
        u.y = *reinterpret_cast<unsigned*>(&h1);
        g_vh[i] = u;
    }
}

// ---------------------------------------------------------------------------
__global__ void k_hist(const int* __restrict__ row, int e) {
    for (int i = blockIdx.x * blockDim.x + threadIdx.x; i < e;
         i += gridDim.x * blockDim.x) {
        atomicAdd(&g_cnt[__ldcs(&row[i])], 1);
    }
}

// ---------------------------------------------------------------------------
__global__ void k_scan_a(int n) {
    __shared__ int wsum[32];
    int t = threadIdx.x, lane = t & 31, warp = t >> 5;
    int i = blockIdx.x * SCAN_THREADS + t;
    int v = (i < n) ? g_cnt[i] : 0;
    int s = v;
#pragma unroll
    for (int o = 16; o; o >>= 1) s += __shfl_down_sync(FULLMASK, s, o);
    if (!lane) wsum[warp] = s;
    __syncthreads();
    if (warp == 0) {
        int x = wsum[lane];
#pragma unroll
        for (int o = 16; o; o >>= 1) x += __shfl_down_sync(FULLMASK, x, o);
        if (!lane) g_bsum[blockIdx.x] = x;
    }
}

__global__ void k_scan_b(int n, int e) {
    __shared__ int ws[4];
    int t = threadIdx.x, lane = t & 31, warp = t >> 5;   // 128 threads
    int v = g_bsum[t];
    int inc = v;
#pragma unroll
    for (int o = 1; o < 32; o <<= 1) {
        int u = __shfl_up_sync(FULLMASK, inc, o);
        if (lane >= o) inc += u;
    }
    if (lane == 31) ws[warp] = inc;
    __syncthreads();
    if (t == 0) {
        int run = 0;
        for (int j = 0; j < 4; j++) { int x = ws[j]; ws[j] = run; run += x; }
        g_off[n] = e;
    }
    __syncthreads();
    g_bbase[t] = ws[warp] + (inc - v);
}

__global__ void k_scan_c(int n) {
    __shared__ int wsum[32];
    int t = threadIdx.x, lane = t & 31, warp = t >> 5;
    int i = blockIdx.x * SCAN_THREADS + t;
    int v = (i < n) ? g_cnt[i] : 0;
    int inc = v;
#pragma unroll
    for (int o = 1; o < 32; o <<= 1) {
        int u = __shfl_up_sync(FULLMASK, inc, o);
        if (lane >= o) inc += u;
    }
    if (lane == 31) wsum[warp] = inc;
    __syncthreads();
    if (warp == 0) {
        int x = wsum[lane];
        int winc = x;
#pragma unroll
        for (int o = 1; o < 32; o <<= 1) {
            int u = __shfl_up_sync(FULLMASK, winc, o);
            if (lane >= o) winc += u;
        }
        wsum[lane] = winc - x;
    }
    __syncthreads();
    int run = g_bbase[blockIdx.x] + wsum[warp] + (inc - v);
    if (i < n) {
        g_off[i] = run;
        g_cnt[i] = run;
    }
}

// ---------------------------------------------------------------------------
__global__ void k_scatter(const int* __restrict__ row,
                          const int* __restrict__ col,
                          const float* __restrict__ adj, int e) {
    float pab = 0.f, pa2 = 0.f, pb2 = 0.f;
    for (int i = blockIdx.x * blockDim.x + threadIdx.x; i < e;
         i += gridDim.x * blockDim.x) {
        int r = __ldcs(&row[i]), c = __ldcs(&col[i]);
        int pos = atomicAdd(&g_cnt[r], 1);
        pos = min(max(pos, 0), MAXE - 1);
        g_edge[pos] = make_int2(c, __float_as_int(__ldcs(&adj[i])));
        float a = g_me[r], b = g_me[c];
        pab = fmaf(a, b, pab);
        pa2 = fmaf(a, a, pa2);
        pb2 = fmaf(b, b, pb2);
    }
#pragma unroll
    for (int o = 16; o; o >>= 1) {
        pab += __shfl_down_sync(FULLMASK, pab, o);
        pa2 += __shfl_down_sync(FULLMASK, pa2, o);
        pb2 += __shfl_down_sync(FULLMASK, pb2, o);
    }
    __shared__ float sb[3][8];
    int w = threadIdx.x >> 5, l = threadIdx.x & 31;
    if (!l) { sb[0][w] = pab; sb[1][w] = pa2; sb[2][w] = pb2; }
    __syncthreads();
    if (!threadIdx.x) {
        float t0 = 0.f, t1 = 0.f, t2 = 0.f;
        int nw = blockDim.x >> 5;
        for (int j = 0; j < nw; j++) { t0 += sb[0][j]; t1 += sb[1][j]; t2 += sb[2][j]; }
        atomicAdd(&g_acc[0], t0);
        atomicAdd(&g_acc[1], t1);
        atomicAdd(&g_acc[2], t2);
    }
}

// ---------------------------------------------------------------------------
__global__ void k_par(const float* __restrict__ lambda0,
                      const float* __restrict__ gamma) {
    if (threadIdx.x == 0) {
        float sab = g_acc[0], sa2 = g_acc[1], sb2 = g_acc[2];
        float na = fmaxf(sqrtf(sa2), 1e-8f);
        float nb = fmaxf(sqrtf(sb2), 1e-8f);
        g_par[0] = expf(lambda0[0]);
        g_par[1] = gamma[0] * (sab / (na * nb));
    }
}

// ---------------------------------------------------------------------------
// K4: DUAL-EDGE per-row kernel with restored DEPTH-1 SOFTWARE PIPELINE:
// at pair t, the four gathers (ku/ec/vuA/vuB) for pair t+1 are issued
// before processing pair t — the ~250cyc L2 hit latency is overlapped
// with compute instead of exposed per iteration.
// ---------------------------------------------------------------------------
__global__ void __launch_bounds__(256)
k_main(const float4* __restrict__ q4, const float2* __restrict__ eig2,
       float4* __restrict__ out4, int n, int e) {
    int wid  = (blockIdx.x * blockDim.x + threadIdx.x) >> 5;
    int lane = threadIdx.x & 31;
    if (wid >= n) return;
    int start = g_off[wid];
    int end   = g_off[wid + 1];
    start = min(max(start, 0), e);
    end   = min(max(end, start), e);

    float4 zero = make_float4(0.f, 0.f, 0.f, 0.f);
    if (start == end) {
        out4[wid * 32 + lane] = zero;
        return;
    }
    unsigned long long pol = mk_policy_el();
    const float inv = 0.08838834764831845f;  // 1/sqrt(128)
    float c   = g_par[1];
    float lam = g_par[0];
    int  sub  = lane & 15;
    int  grp  = lane >> 4;        // 0 = edge A, 1 = edge B

    float4 qa = __ldcs(&q4[wid * 32 + 2 * sub]);
    float4 qb = __ldcs(&q4[wid * 32 + 2 * sub + 1]);
    qa.x *= inv; qa.y *= inv; qa.z *= inv; qa.w *= inv;
    qb.x *= inv; qb.y *= inv; qb.z *= inv; qb.w *= inv;
    float2 er = ldg_el_f2(&eig2[wid * 16 + sub], pol);
    float lerx = lam * er.x, lery = lam * er.y;

    float  m0 = -INFINITY, z0 = 0.f;
    float  m1 = -INFINITY, z1 = 0.f;
    float4 a0 = zero, a1 = zero;

    for (int base = start; base < end; base += 32) {
        int nb = end - base; if (nb > 32) nb = 32;
        int2 ea = (lane < nb) ? __ldcs(&g_edge[base + lane]) : make_int2(0, 0);
        int   bc = min(max(ea.x, 0), n - 1);
        float ba = __int_as_float(ea.y);
        int npairs = (nb + 1) >> 1;          // warp-uniform

        // ---- pipeline prologue: issue loads for pair 0 ----
        int   cA = __shfl_sync(FULLMASK, bc, 0);
        int   cB = __shfl_sync(FULLMASK, bc, (1 < nb) ? 1 : 0);
        int   cg = grp ? cB : cA;
        uint4  ku  = ldg_el_u4(&g_kh4[cg * 16 + sub], pol);
        float2 ec  = ldg_el_f2(&eig2[cg * 16 + sub], pol);
        uint2  vuA = ldg_el_u2(&g_vh[cA * 32 + lane], pol);
        uint2  vuB = ldg_el_u2(&g_vh[cB * 32 + lane], pol);

        for (int t = 0; t < npairs; t++) {
            int iA = 2 * t, iB = 2 * t + 1;
            bool hasB = iB < nb;             // warp-uniform
            float adjA = __shfl_sync(FULLMASK, ba, iA);
            float adjB = __shfl_sync(FULLMASK, ba, hasB ? iB : iA);

            // ---- issue loads for pair t+1 (dup last pair on tail) ----
            int tn = (t + 1 < npairs) ? t + 1 : t;
            int jA = 2 * tn;
            int jB = (2 * tn + 1 < nb) ? 2 * tn + 1 : jA;
            int   cA2 = __shfl_sync(FULLMASK, bc, jA);
            int   cB2 = __shfl_sync(FULLMASK, bc, jB);
            int   cg2 = grp ? cB2 : cA2;
            uint4  ku2  = ldg_el_u4(&g_kh4[cg2 * 16 + sub], pol);
            float2 ec2  = ldg_el_f2(&eig2[cg2 * 16 + sub], pol);
            uint2  vuA2 = ldg_el_u2(&g_vh[cA2 * 32 + lane], pol);
            uint2  vuB2 = ldg_el_u2(&g_vh[cB2 * 32 + lane], pol);

            // ---- process pair t from staged registers ----
            __half2 h0 = *reinterpret_cast<__half2*>(&ku.x);
            __half2 h1 = *reinterpret_cast<__half2*>(&ku.y);
            __half2 h2 = *reinterpret_cast<__half2*>(&ku.z);
            __half2 h3 = *reinterpret_cast<__half2*>(&ku.w);
            float2 k01 = __half22float2(h0);
            float2 k23 = __half22float2(h1);
            float2 k45 = __half22float2(h2);
            float2 k67 = __half22float2(h3);

            float part = fmaf(qa.x, k01.x,
                         fmaf(qa.y, k01.y,
                         fmaf(qa.z, k23.x,
                         fmaf(qa.w, k23.y,
                         fmaf(qb.x, k45.x,
                         fmaf(qb.y, k45.y,
                         fmaf(qb.z, k67.x,
                         fmaf(qb.w, k67.y,
                         fmaf(lerx, ec.x, lery * ec.y)))))))));
            part += __shfl_xor_sync(FULLMASK, part, 1);
            part += __shfl_xor_sync(FULLMASK, part, 2);
            part += __shfl_xor_sync(FULLMASK, part, 4);
            part += __shfl_xor_sync(FULLMASK, part, 8);
            float so = __shfl_xor_sync(FULLMASK, part, 16);
            float sA = grp ? so : part;
            float sB = grp ? part : so;
            if (!hasB) sB = -INFINITY;

            __half2 a0h = *reinterpret_cast<__half2*>(&vuA.x);
            __half2 a1h = *reinterpret_cast<__half2*>(&vuA.y);
            __half2 b0h = *reinterpret_cast<__half2*>(&vuB.x);
            __half2 b1h = *reinterpret_cast<__half2*>(&vuB.y);
            float2 vA01 = __half22float2(a0h);
            float2 vA23 = __half22float2(a1h);
            float2 vB01 = __half22float2(b0h);
            float2 vB23 = __half22float2(b1h);

            float nm0 = fmaxf(m0, fmaxf(sA, sB));
            float f0  = __expf(m0 - nm0);
            float wA0 = __expf(sA - nm0);
            float wB0 = __expf(sB - nm0);
            z0   = fmaf(z0, f0, wA0 + wB0);
            a0.x = fmaf(a0.x, f0, fmaf(wA0, vA01.x, wB0 * vB01.x));
            a0.y = fmaf(a0.y, f0, fmaf(wA0, vA01.y, wB0 * vB01.y));
            a0.z = fmaf(a0.z, f0, fmaf(wA0, vA23.x, wB0 * vB23.x));
            a0.w = fmaf(a0.w, f0, fmaf(wA0, vA23.y, wB0 * vB23.y));
            m0 = nm0;

            float s1A = c * adjA;
            float s1B = hasB ? c * adjB : -INFINITY;
            float nm1 = fmaxf(m1, fmaxf(s1A, s1B));
            float f1  = __expf(m1 - nm1);
            float wA1 = __expf(s1A - nm1);
            float wB1 = __expf(s1B - nm1);
            z1   = fmaf(z1, f1, wA1 + wB1);
            a1.x = fmaf(a1.x, f1, fmaf(wA1, vA01.x, wB1 * vB01.x));
            a1.y = fmaf(a1.y, f1, fmaf(wA1, vA01.y, wB1 * vB01.y));
            a1.z = fmaf(a1.z, f1, fmaf(wA1, vA23.x, wB1 * vB23.x));
            a1.w = fmaf(a1.w, f1, fmaf(wA1, vA23.y, wB1 * vB23.y));
            m1 = nm1;

            // rotate pipeline registers
            ku = ku2; ec = ec2; vuA = vuA2; vuB = vuB2;
            cA = cA2; cB = cB2;
        }
    }

    float i0 = 0.5f / z0;
    float i1 = 0.5f / z1;
    float4 o;
    o.x = fmaf(a0.x, i0, a1.x * i1);
    o.y = fmaf(a0.y, i0, a1.y * i1);
    o.z = fmaf(a0.z, i0, a1.z * i1);
    o.w = fmaf(a0.w, i0, a1.w * i1);
    __stcs(&out4[wid * 32 + lane], o);
}

// ---------------------------------------------------------------------------
extern "C" void kernel_launch(void* const* d_in, const int* in_sizes, int n_in,
                              void* d_out, int out_size) {
    const float* q       = (const float*)d_in[0];
    const float* k       = (const float*)d_in[1];
    const float* v       = (const float*)d_in[2];
    const float* eigs    = (const float*)d_in[3];
    const float* adj     = (const float*)d_in[4];
    const float* lambda0 = (const float*)d_in[5];
    const float* gamma   = (const float*)d_in[6];
    const float* memb    = (const float*)d_in[7];
    const int*   row     = (const int*)d_in[8];
    const int*   col     = (const int*)d_in[9];
    const int*   mids    = (const int*)d_in[10];

    int n = in_sizes[10];  // N
    int e = in_sizes[8];   // E

    k_init<<<(n + 255) / 256, 256>>>(memb, mids, n);
    k_pack<<<2048, 256>>>((const float4*)k, (const float4*)v, n);
    k_hist<<<2048, 256>>>(row, e);
    k_scan_a<<<SCAN_BLOCKS, SCAN_THREADS>>>(n);
    k_scan_b<<<1, SCAN_BLOCKS>>>(n, e);
    k_scan_c<<<SCAN_BLOCKS, SCAN_THREADS>>>(n);
    k_scatter<<<2048, 256>>>(row, col, adj, e);
    k_par<<<1, 32>>>(lambda0, gamma);
    k_main<<<(n * 32 + 255) / 256, 256>>>(
        (const float4*)q, (const float2*)eigs, (float4*)d_out, n, e);
}

// round 15
// speedup vs baseline: 1.0949x; 1.0949x over previous
#include <cuda_runtime.h>
#include <cuda_fp16.h>
#include <math.h>

// Problem-fixed sizes: N=100000, E=1600000, D=128, EIG=32.
#define MAXN 100000
#define MAXE 1600000
#define FULLMASK 0xffffffffu
#define SCAN_BLOCKS 128
#define SCAN_THREADS 1024

// Scratch (device globals — explicitly zeroed by k_init every call).
__device__ float g_me[MAXN];
__device__ int   g_cnt[MAXN];
__device__ int   g_off[MAXN + 1];
__device__ float g_acc[3];
__device__ float g_par[2];          // [0]=exp(lambda0), [1]=c = gamma*sim
__device__ int2  g_edge[MAXE];      // (col, adj-as-int) sorted by row
__device__ uint2 g_vh[MAXN * 32];   // v fp16: lane layout, 4 halfs per uint2
__device__ uint4 g_kh4[MAXN * 16];  // k fp16: 8 halfs per uint4 (16-lane layout)
__device__ int   g_bsum[SCAN_BLOCKS];
__device__ int   g_bbase[SCAN_BLOCKS];

// ---- cache-policy-steered load helpers ----
__device__ __forceinline__ unsigned long long mk_policy_el() {
    unsigned long long pol;
    asm("createpolicy.fractional.L2::evict_last.b64 %0, 1.0;" : "=l"(pol));
    return pol;
}
__device__ __forceinline__ float2 ldg_el_f2(const float2* p,
                                            unsigned long long pol) {
    float2 r;
    asm("ld.global.nc.L2::cache_hint.v2.f32 {%0,%1},[%2],%3;"
        : "=f"(r.x), "=f"(r.y) : "l"(p), "l"(pol));
    return r;
}
__device__ __forceinline__ uint2 ldg_el_u2(const uint2* p,
                                           unsigned long long pol) {
    uint2 r;
    asm("ld.global.nc.L2::cache_hint.v2.u32 {%0,%1},[%2],%3;"
        : "=r"(r.x), "=r"(r.y) : "l"(p), "l"(pol));
    return r;
}
__device__ __forceinline__ uint4 ldg_el_u4(const uint4* p,
                                           unsigned long long pol) {
    uint4 r;
    asm("ld.global.nc.L2::cache_hint.v4.u32 {%0,%1,%2,%3},[%4],%5;"
        : "=r"(r.x), "=r"(r.y), "=r"(r.z), "=r"(r.w) : "l"(p), "l"(pol));
    return r;
}

// ---------------------------------------------------------------------------
__global__ void k_init(const float* __restrict__ memb,
                       const int* __restrict__ mids, int n) {
    int i = blockIdx.x * blockDim.x + threadIdx.x;
    if (i == 0) { g_acc[0] = 0.f; g_acc[1] = 0.f; g_acc[2] = 0.f; }
    if (i < n) {
        g_me[i]  = memb[__ldcs(&mids[i])];
        g_cnt[i] = 0;
    }
}

// ---------------------------------------------------------------------------
__global__ void k_pack(const float4* __restrict__ k4,
                       const float4* __restrict__ v4, int n) {
    int n16 = n * 16, n32 = n * 32;
    for (int i = blockIdx.x * blockDim.x + threadIdx.x; i < n16;
         i += gridDim.x * blockDim.x) {
        float4 a = __ldcs(&k4[2 * i]);
        float4 b = __ldcs(&k4[2 * i + 1]);
        __half2 h0 = __floats2half2_rn(a.x, a.y);
        __half2 h1 = __floats2half2_rn(a.z, a.w);
        __half2 h2 = __floats2half2_rn(b.x, b.y);
        __half2 h3 = __floats2half2_rn(b.z, b.w);
        uint4 u;
        u.x = *reinterpret_cast<unsigned*>(&h0);
        u.y = *reinterpret_cast<unsigned*>(&h1);
        u.z = *reinterpret_cast<unsigned*>(&h2);
        u.w = *reinterpret_cast<unsigned*>(&h3);
        g_kh4[i] = u;
    }
    for (int i = blockIdx.x * blockDim.x + threadIdx.x; i < n32;
         i += gridDim.x * blockDim.x) {
        float4 vv = __ldcs(&v4[i]);
        __half2 h0 = __floats2half2_rn(vv.x, vv.y);
        __half2 h1 = __floats2half2_rn(vv.z, vv.w);
        uint2 u;
        u.x = *reinterpret_cast<unsigned*>(&h0);
        u.y = *reinterpret_cast<unsigned*>(&h1);
        g_vh[i] = u;
    }
}

// ---------------------------------------------------------------------------
__global__ void k_hist(const int* __restrict__ row, int e) {
    for (int i = blockIdx.x * blockDim.x + threadIdx.x; i < e;
         i += gridDim.x * blockDim.x) {
        atomicAdd(&g_cnt[__ldcs(&row[i])], 1);
    }
}

// ---------------------------------------------------------------------------
__global__ void k_scan_a(int n) {
    __shared__ int wsum[32];
    int t = threadIdx.x, lane = t & 31, warp = t >> 5;
    int i = blockIdx.x * SCAN_THREADS + t;
    int v = (i < n) ? g_cnt[i] : 0;
    int s = v;
#pragma unroll
    for (int o = 16; o; o >>= 1) s += __shfl_down_sync(FULLMASK, s, o);
    if (!lane) wsum[warp] = s;
    __syncthreads();
    if (warp == 0) {
        int x = wsum[lane];
#pragma unroll
        for (int o = 16; o; o >>= 1) x += __shfl_down_sync(FULLMASK, x, o);
        if (!lane) g_bsum[blockIdx.x] = x;
    }
}

__global__ void k_scan_b(int n, int e) {
    __shared__ int ws[4];
    int t = threadIdx.x, lane = t & 31, warp = t >> 5;   // 128 threads
    int v = g_bsum[t];
    int inc = v;
#pragma unroll
    for (int o = 1; o < 32; o <<= 1) {
        int u = __shfl_up_sync(FULLMASK, inc, o);
        if (lane >= o) inc += u;
    }
    if (lane == 31) ws[warp] = inc;
    __syncthreads();
    if (t == 0) {
        int run = 0;
        for (int j = 0; j < 4; j++) { int x = ws[j]; ws[j] = run; run += x; }
        g_off[n] = e;
    }
    __syncthreads();
    g_bbase[t] = ws[warp] + (inc - v);
}

__global__ void k_scan_c(int n) {
    __shared__ int wsum[32];
    int t = threadIdx.x, lane = t & 31, warp = t >> 5;
    int i = blockIdx.x * SCAN_THREADS + t;
    int v = (i < n) ? g_cnt[i] : 0;
    int inc = v;
#pragma unroll
    for (int o = 1; o < 32; o <<= 1) {
        int u = __shfl_up_sync(FULLMASK, inc, o);
        if (lane >= o) inc += u;
    }
    if (lane == 31) wsum[warp] = inc;
    __syncthreads();
    if (warp == 0) {
        int x = wsum[lane];
        int winc = x;
#pragma unroll
        for (int o = 1; o < 32; o <<= 1) {
            int u = __shfl_up_sync(FULLMASK, winc, o);
            if (lane >= o) winc += u;
        }
        wsum[lane] = winc - x;
    }
    __syncthreads();
    int run = g_bbase[blockIdx.x] + wsum[warp] + (inc - v);
    if (i < n) {
        g_off[i] = run;
        g_cnt[i] = run;
    }
}

// ---------------------------------------------------------------------------
__global__ void k_scatter(const int* __restrict__ row,
                          const int* __restrict__ col,
                          const float* __restrict__ adj, int e) {
    float pab = 0.f, pa2 = 0.f, pb2 = 0.f;
    for (int i = blockIdx.x * blockDim.x + threadIdx.x; i < e;
         i += gridDim.x * blockDim.x) {
        int r = __ldcs(&row[i]), c = __ldcs(&col[i]);
        int pos = atomicAdd(&g_cnt[r], 1);
        pos = min(max(pos, 0), MAXE - 1);
        g_edge[pos] = make_int2(c, __float_as_int(__ldcs(&adj[i])));
        float a = g_me[r], b = g_me[c];
        pab = fmaf(a, b, pab);
        pa2 = fmaf(a, a, pa2);
        pb2 = fmaf(b, b, pb2);
    }
#pragma unroll
    for (int o = 16; o; o >>= 1) {
        pab += __shfl_down_sync(FULLMASK, pab, o);
        pa2 += __shfl_down_sync(FULLMASK, pa2, o);
        pb2 += __shfl_down_sync(FULLMASK, pb2, o);
    }
    __shared__ float sb[3][8];
    int w = threadIdx.x >> 5, l = threadIdx.x & 31;
    if (!l) { sb[0][w] = pab; sb[1][w] = pa2; sb[2][w] = pb2; }
    __syncthreads();
    if (!threadIdx.x) {
        float t0 = 0.f, t1 = 0.f, t2 = 0.f;
        int nw = blockDim.x >> 5;
        for (int j = 0; j < nw; j++) { t0 += sb[0][j]; t1 += sb[1][j]; t2 += sb[2][j]; }
        atomicAdd(&g_acc[0], t0);
        atomicAdd(&g_acc[1], t1);
        atomicAdd(&g_acc[2], t2);
    }
}

// ---------------------------------------------------------------------------
__global__ void k_par(const float* __restrict__ lambda0,
                      const float* __restrict__ gamma) {
    if (threadIdx.x == 0) {
        float sab = g_acc[0], sa2 = g_acc[1], sb2 = g_acc[2];
        float na = fmaxf(sqrtf(sa2), 1e-8f);
        float nb = fmaxf(sqrtf(sb2), 1e-8f);
        g_par[0] = expf(lambda0[0]);
        g_par[1] = gamma[0] * (sab / (na * nb));
    }
}

// ---------------------------------------------------------------------------
// K4: DUAL-EDGE per-row kernel, MAX-FREE softmax. Scores here are bounded
// (|s0| <~ 35 << 88, |s1| <~ 1), so exp cannot overflow and the max-
// subtraction is dropped: w = exp(s), z += w, a += w*v — no loop-carried
// fmax→exp→rescale chain, accumulators pipeline as plain FFMA.
// (Structure = R13 winner; NO manual pipeline — R14 showed it regresses.)
// ---------------------------------------------------------------------------
__global__ void __launch_bounds__(256)
k_main(const float4* __restrict__ q4, const float2* __restrict__ eig2,
       float4* __restrict__ out4, int n, int e) {
    int wid  = (blockIdx.x * blockDim.x + threadIdx.x) >> 5;
    int lane = threadIdx.x & 31;
    if (wid >= n) return;
    int start = g_off[wid];
    int end   = g_off[wid + 1];
    start = min(max(start, 0), e);
    end   = min(max(end, start), e);

    float4 zero = make_float4(0.f, 0.f, 0.f, 0.f);
    if (start == end) {
        out4[wid * 32 + lane] = zero;
        return;
    }
    unsigned long long pol = mk_policy_el();
    const float inv = 0.08838834764831845f;  // 1/sqrt(128)
    float c   = g_par[1];
    float lam = g_par[0];
    int  sub  = lane & 15;
    int  grp  = lane >> 4;        // 0 = edge A, 1 = edge B

    float4 qa = __ldcs(&q4[wid * 32 + 2 * sub]);
    float4 qb = __ldcs(&q4[wid * 32 + 2 * sub + 1]);
    qa.x *= inv; qa.y *= inv; qa.z *= inv; qa.w *= inv;
    qb.x *= inv; qb.y *= inv; qb.z *= inv; qb.w *= inv;
    float2 er = ldg_el_f2(&eig2[wid * 16 + sub], pol);
    float lerx = lam * er.x, lery = lam * er.y;

    float  z0 = 0.f, z1 = 0.f;
    float4 a0 = zero, a1 = zero;

    for (int base = start; base < end; base += 32) {
        int nb = end - base; if (nb > 32) nb = 32;
        int2 ea = (lane < nb) ? __ldcs(&g_edge[base + lane]) : make_int2(0, 0);
        int   bc = min(max(ea.x, 0), n - 1);
        float ba = __int_as_float(ea.y);

        for (int t = 0; 2 * t < nb; t++) {      // warp-uniform trip count
            int iA = 2 * t, iB = 2 * t + 1;
            bool hasB = iB < nb;                // warp-uniform
            int   cA   = __shfl_sync(FULLMASK, bc, iA);
            int   cB   = __shfl_sync(FULLMASK, bc, iB);
            float adjA = __shfl_sync(FULLMASK, ba, iA);
            float adjB = __shfl_sync(FULLMASK, ba, iB);
            int   cg   = grp ? cB : cA;

            uint4  ku = ldg_el_u4(&g_kh4[cg * 16 + sub], pol);
            float2 ec = ldg_el_f2(&eig2[cg * 16 + sub], pol);
            uint2  vuA = ldg_el_u2(&g_vh[cA * 32 + lane], pol);
            uint2  vuB = ldg_el_u2(&g_vh[cB * 32 + lane], pol);

            __half2 h0 = *reinterpret_cast<__half2*>(&ku.x);
            __half2 h1 = *reinterpret_cast<__half2*>(&ku.y);
            __half2 h2 = *reinterpret_cast<__half2*>(&ku.z);
            __half2 h3 = *reinterpret_cast<__half2*>(&ku.w);
            float2 k01 = __half22float2(h0);
            float2 k23 = __half22float2(h1);
            float2 k45 = __half22float2(h2);
            float2 k67 = __half22float2(h3);

            float part = fmaf(qa.x, k01.x,
                         fmaf(qa.y, k01.y,
                         fmaf(qa.z, k23.x,
                         fmaf(qa.w, k23.y,
                         fmaf(qb.x, k45.x,
                         fmaf(qb.y, k45.y,
                         fmaf(qb.z, k67.x,
                         fmaf(qb.w, k67.y,
                         fmaf(lerx, ec.x, lery * ec.y)))))))));
            part += __shfl_xor_sync(FULLMASK, part, 1);
            part += __shfl_xor_sync(FULLMASK, part, 2);
            part += __shfl_xor_sync(FULLMASK, part, 4);
            part += __shfl_xor_sync(FULLMASK, part, 8);
            float so = __shfl_xor_sync(FULLMASK, part, 16);
            float sA = grp ? so : part;
            float sB = grp ? part : so;
            if (!hasB) sB = -INFINITY;          // exp(-inf) = 0 kills tail

            __half2 a0h = *reinterpret_cast<__half2*>(&vuA.x);
            __half2 a1h = *reinterpret_cast<__half2*>(&vuA.y);
            __half2 b0h = *reinterpret_cast<__half2*>(&vuB.x);
            __half2 b1h = *reinterpret_cast<__half2*>(&vuB.y);
            float2 vA01 = __half22float2(a0h);
            float2 vA23 = __half22float2(a1h);
            float2 vB01 = __half22float2(b0h);
            float2 vB23 = __half22float2(b1h);

            // branch 0: max-free softmax accumulation
            float wA0 = __expf(sA);
            float wB0 = __expf(sB);
            z0  += wA0 + wB0;
            a0.x = fmaf(wA0, vA01.x, fmaf(wB0, vB01.x, a0.x));
            a0.y = fmaf(wA0, vA01.y, fmaf(wB0, vB01.y, a0.y));
            a0.z = fmaf(wA0, vA23.x, fmaf(wB0, vB23.x, a0.z));
            a0.w = fmaf(wA0, vA23.y, fmaf(wB0, vB23.y, a0.w));

            // branch 1: |c*adj| <= ~1 — trivially safe
            float wA1 = __expf(c * adjA);
            float wB1 = hasB ? __expf(c * adjB) : 0.f;
            z1  += wA1 + wB1;
            a1.x = fmaf(wA1, vA01.x, fmaf(wB1, vB01.x, a1.x));
            a1.y = fmaf(wA1, vA01.y, fmaf(wB1, vB01.y, a1.y));
            a1.z = fmaf(wA1, vA23.x, fmaf(wB1, vB23.x, a1.z));
            a1.w = fmaf(wA1, vA23.y, fmaf(wB1, vB23.y, a1.w));
        }
    }

    float i0 = 0.5f / z0;
    float i1 = 0.5f / z1;
    float4 o;
    o.x = fmaf(a0.x, i0, a1.x * i1);
    o.y = fmaf(a0.y, i0, a1.y * i1);
    o.z = fmaf(a0.z, i0, a1.z * i1);
    o.w = fmaf(a0.w, i0, a1.w * i1);
    __stcs(&out4[wid * 32 + lane], o);
}

// ---------------------------------------------------------------------------
extern "C" void kernel_launch(void* const* d_in, const int* in_sizes, int n_in,
                              void* d_out, int out_size) {
    const float* q       = (const float*)d_in[0];
    const float* k       = (const float*)d_in[1];
    const float* v       = (const float*)d_in[2];
    const float* eigs    = (const float*)d_in[3];
    const float* adj     = (const float*)d_in[4];
    const float* lambda0 = (const float*)d_in[5];
    const float* gamma   = (const float*)d_in[6];
    const float* memb    = (const float*)d_in[7];
    const int*   row     = (const int*)d_in[8];
    const int*   col     = (const int*)d_in[9];
    const int*   mids    = (const int*)d_in[10];

    int n = in_sizes[10];  // N
    int e = in_sizes[8];   // E

    k_init<<<(n + 255) / 256, 256>>>(memb, mids, n);
    k_pack<<<2048, 256>>>((const float4*)k, (const float4*)v, n);
    k_hist<<<2048, 256>>>(row, e);
    k_scan_a<<<SCAN_BLOCKS, SCAN_THREADS>>>(n);
    k_scan_b<<<1, SCAN_BLOCKS>>>(n, e);
    k_scan_c<<<SCAN_BLOCKS, SCAN_THREADS>>>(n);
    k_scatter<<<2048, 256>>>(row, col, adj, e);
    k_par<<<1, 32>>>(lambda0, gamma);
    k_main<<<(n * 32 + 255) / 256, 256>>>(
        (const float4*)q, (const float2*)eigs, (float4*)d_out, n, e);
}

// round 16
// speedup vs baseline: 1.1311x; 1.0331x over previous
#include <cuda_runtime.h>
#include <cuda_fp16.h>
#include <math.h>

// Problem-fixed sizes: N=100000, E=1600000, D=128, EIG=32.
#define MAXN 100000
#define MAXE 1600000
#define FULLMASK 0xffffffffu
#define SCAN_BLOCKS 128
#define SCAN_THREADS 1024

// Scratch (device globals — explicitly zeroed by k_init every call).
__device__ float g_me[MAXN];
__device__ int   g_cnt[MAXN];
__device__ int   g_off[MAXN + 1];
__device__ float g_acc[3];
__device__ float g_par[2];          // [0]=exp(lambda0), [1]=c = gamma*sim
__device__ int2  g_edge[MAXE];      // (col, adj-as-int) sorted by row
__device__ uint2 g_vh[MAXN * 32];   // v fp16 (also read as uint4[N*16])
__device__ uint4 g_kh4[MAXN * 16];  // k fp16: 8 halfs per uint4 (16-lane layout)
__device__ int   g_bsum[SCAN_BLOCKS];
__device__ int   g_bbase[SCAN_BLOCKS];

// ---- cache-policy-steered load helpers ----
__device__ __forceinline__ unsigned long long mk_policy_el() {
    unsigned long long pol;
    asm("createpolicy.fractional.L2::evict_last.b64 %0, 1.0;" : "=l"(pol));
    return pol;
}
__device__ __forceinline__ float2 ldg_el_f2(const float2* p,
                                            unsigned long long pol) {
    float2 r;
    asm("ld.global.nc.L2::cache_hint.v2.f32 {%0,%1},[%2],%3;"
        : "=f"(r.x), "=f"(r.y) : "l"(p), "l"(pol));
    return r;
}
__device__ __forceinline__ uint4 ldg_el_u4(const uint4* p,
                                           unsigned long long pol) {
    uint4 r;
    asm("ld.global.nc.L2::cache_hint.v4.u32 {%0,%1,%2,%3},[%4],%5;"
        : "=r"(r.x), "=r"(r.y), "=r"(r.z), "=r"(r.w) : "l"(p), "l"(pol));
    return r;
}

// ---------------------------------------------------------------------------
__global__ void k_init(const float* __restrict__ memb,
                       const int* __restrict__ mids, int n) {
    int i = blockIdx.x * blockDim.x + threadIdx.x;
    if (i == 0) { g_acc[0] = 0.f; g_acc[1] = 0.f; g_acc[2] = 0.f; }
    if (i < n) {
        g_me[i]  = memb[__ldcs(&mids[i])];
        g_cnt[i] = 0;
    }
}

// ---------------------------------------------------------------------------
__global__ void k_pack(const float4* __restrict__ k4,
                       const float4* __restrict__ v4, int n) {
    int n16 = n * 16, n32 = n * 32;
    for (int i = blockIdx.x * blockDim.x + threadIdx.x; i < n16;
         i += gridDim.x * blockDim.x) {
        float4 a = __ldcs(&k4[2 * i]);
        float4 b = __ldcs(&k4[2 * i + 1]);
        __half2 h0 = __floats2half2_rn(a.x, a.y);
        __half2 h1 = __floats2half2_rn(a.z, a.w);
        __half2 h2 = __floats2half2_rn(b.x, b.y);
        __half2 h3 = __floats2half2_rn(b.z, b.w);
        uint4 u;
        u.x = *reinterpret_cast<unsigned*>(&h0);
        u.y = *reinterpret_cast<unsigned*>(&h1);
        u.z = *reinterpret_cast<unsigned*>(&h2);
        u.w = *reinterpret_cast<unsigned*>(&h3);
        g_kh4[i] = u;
    }
    for (int i = blockIdx.x * blockDim.x + threadIdx.x; i < n32;
         i += gridDim.x * blockDim.x) {
        float4 vv = __ldcs(&v4[i]);
        __half2 h0 = __floats2half2_rn(vv.x, vv.y);
        __half2 h1 = __floats2half2_rn(vv.z, vv.w);
        uint2 u;
        u.x = *reinterpret_cast<unsigned*>(&h0);
        u.y = *reinterpret_cast<unsigned*>(&h1);
        g_vh[i] = u;
    }
}

// ---------------------------------------------------------------------------
__global__ void k_hist(const int* __restrict__ row, int e) {
    for (int i = blockIdx.x * blockDim.x + threadIdx.x; i < e;
         i += gridDim.x * blockDim.x) {
        atomicAdd(&g_cnt[__ldcs(&row[i])], 1);
    }
}

// ---------------------------------------------------------------------------
__global__ void k_scan_a(int n) {
    __shared__ int wsum[32];
    int t = threadIdx.x, lane = t & 31, warp = t >> 5;
    int i = blockIdx.x * SCAN_THREADS + t;
    int v = (i < n) ? g_cnt[i] : 0;
    int s = v;
#pragma unroll
    for (int o = 16; o; o >>= 1) s += __shfl_down_sync(FULLMASK, s, o);
    if (!lane) wsum[warp] = s;
    __syncthreads();
    if (warp == 0) {
        int x = wsum[lane];
#pragma unroll
        for (int o = 16; o; o >>= 1) x += __shfl_down_sync(FULLMASK, x, o);
        if (!lane) g_bsum[blockIdx.x] = x;
    }
}

__global__ void k_scan_b(int n, int e) {
    __shared__ int ws[4];
    int t = threadIdx.x, lane = t & 31, warp = t >> 5;   // 128 threads
    int v = g_bsum[t];
    int inc = v;
#pragma unroll
    for (int o = 1; o < 32; o <<= 1) {
        int u = __shfl_up_sync(FULLMASK, inc, o);
        if (lane >= o) inc += u;
    }
    if (lane == 31) ws[warp] = inc;
    __syncthreads();
    if (t == 0) {
        int run = 0;
        for (int j = 0; j < 4; j++) { int x = ws[j]; ws[j] = run; run += x; }
        g_off[n] = e;
    }
    __syncthreads();
    g_bbase[t] = ws[warp] + (inc - v);
}

__global__ void k_scan_c(int n) {
    __shared__ int wsum[32];
    int t = threadIdx.x, lane = t & 31, warp = t >> 5;
    int i = blockIdx.x * SCAN_THREADS + t;
    int v = (i < n) ? g_cnt[i] : 0;
    int inc = v;
#pragma unroll
    for (int o = 1; o < 32; o <<= 1) {
        int u = __shfl_up_sync(FULLMASK, inc, o);
        if (lane >= o) inc += u;
    }
    if (lane == 31) wsum[warp] = inc;
    __syncthreads();
    if (warp == 0) {
        int x = wsum[lane];
        int winc = x;
#pragma unroll
        for (int o = 1; o < 32; o <<= 1) {
            int u = __shfl_up_sync(FULLMASK, winc, o);
            if (lane >= o) winc += u;
        }
        wsum[lane] = winc - x;
    }
    __syncthreads();
    int run = g_bbase[blockIdx.x] + wsum[warp] + (inc - v);
    if (i < n) {
        g_off[i] = run;
        g_cnt[i] = run;
    }
}

// ---------------------------------------------------------------------------
__global__ void k_scatter(const int* __restrict__ row,
                          const int* __restrict__ col,
                          const float* __restrict__ adj, int e) {
    float pab = 0.f, pa2 = 0.f, pb2 = 0.f;
    for (int i = blockIdx.x * blockDim.x + threadIdx.x; i < e;
         i += gridDim.x * blockDim.x) {
        int r = __ldcs(&row[i]), c = __ldcs(&col[i]);
        int pos = atomicAdd(&g_cnt[r], 1);
        pos = min(max(pos, 0), MAXE - 1);
        g_edge[pos] = make_int2(c, __float_as_int(__ldcs(&adj[i])));
        float a = g_me[r], b = g_me[c];
        pab = fmaf(a, b, pab);
        pa2 = fmaf(a, a, pa2);
        pb2 = fmaf(b, b, pb2);
    }
#pragma unroll
    for (int o = 16; o; o >>= 1) {
        pab += __shfl_down_sync(FULLMASK, pab, o);
        pa2 += __shfl_down_sync(FULLMASK, pa2, o);
        pb2 += __shfl_down_sync(FULLMASK, pb2, o);
    }
    __shared__ float sb[3][8];
    int w = threadIdx.x >> 5, l = threadIdx.x & 31;
    if (!l) { sb[0][w] = pab; sb[1][w] = pa2; sb[2][w] = pb2; }
    __syncthreads();
    if (!threadIdx.x) {
        float t0 = 0.f, t1 = 0.f, t2 = 0.f;
        int nw = blockDim.x >> 5;
        for (int j = 0; j < nw; j++) { t0 += sb[0][j]; t1 += sb[1][j]; t2 += sb[2][j]; }
        atomicAdd(&g_acc[0], t0);
        atomicAdd(&g_acc[1], t1);
        atomicAdd(&g_acc[2], t2);
    }
}

// ---------------------------------------------------------------------------
__global__ void k_par(const float* __restrict__ lambda0,
                      const float* __restrict__ gamma) {
    if (threadIdx.x == 0) {
        float sab = g_acc[0], sa2 = g_acc[1], sb2 = g_acc[2];
        float na = fmaxf(sqrtf(sa2), 1e-8f);
        float nb = fmaxf(sqrtf(sb2), 1e-8f);
        g_par[0] = expf(lambda0[0]);
        g_par[1] = gamma[0] * (sab / (na * nb));
    }
}

// ---------------------------------------------------------------------------
// K4: SPLIT-GROUP dual-edge kernel. Each 16-lane group fully owns one edge
// of the pair: loads its own edge record (8B broadcast load replaces 4
// shuffles), computes only its own exp (2/pair vs 4), accumulates its
// edge's v (8 fp16-halfs/lane via uint4) into private 8-float accumulators
// per branch (16 FMA/pair vs 32). No xor16 score swap, no 32-block edge
// staging. Groups merge once per row (18 xor16 shuffles, amortized).
// Max-free softmax retained (scores bounded, |s|<~35<<88).
// ---------------------------------------------------------------------------
__global__ void __launch_bounds__(256)
k_main(const float4* __restrict__ q4, const float2* __restrict__ eig2,
       float4* __restrict__ out4, int n, int e) {
    int wid  = (blockIdx.x * blockDim.x + threadIdx.x) >> 5;
    int lane = threadIdx.x & 31;
    if (wid >= n) return;
    int start = g_off[wid];
    int end   = g_off[wid + 1];
    start = min(max(start, 0), e);
    end   = min(max(end, start), e);

    int sub  = lane & 15;
    int grp  = lane >> 4;                    // 0 = edge A, 1 = edge B
    int oidx = wid * 32 + 2 * sub + grp;     // this lane's output float4

    float4 zero = make_float4(0.f, 0.f, 0.f, 0.f);
    if (start == end) {
        out4[oidx] = zero;
        return;
    }
    unsigned long long pol = mk_policy_el();
    const float inv = 0.08838834764831845f;  // 1/sqrt(128)
    float cpar = g_par[1];
    float lam  = g_par[0];

    // lane sub owns q halfs [8sub,8sub+8) and eig comps [2sub,2sub+2)
    float4 qa = __ldcs(&q4[wid * 32 + 2 * sub]);
    float4 qb = __ldcs(&q4[wid * 32 + 2 * sub + 1]);
    qa.x *= inv; qa.y *= inv; qa.z *= inv; qa.w *= inv;
    qb.x *= inv; qb.y *= inv; qb.z *= inv; qb.w *= inv;
    float2 er = ldg_el_f2(&eig2[wid * 16 + sub], pol);
    float lerx = lam * er.x, lery = lam * er.y;

    const uint4* vh4 = reinterpret_cast<const uint4*>(g_vh);

    float z0 = 0.f, z1 = 0.f;
    float a0[8], a1[8];
#pragma unroll
    for (int j = 0; j < 8; j++) { a0[j] = 0.f; a1[j] = 0.f; }

    for (int i = start; i < end; i += 2) {
        bool hasB = (i + 1 < end);           // warp-uniform
        int  ei = i + grp;                   // my group's edge
        if (ei >= end) ei = i;               // tail: group B dups A (killed below)
        int2 eg = g_edge[ei];                // 16-lane broadcast load
        int   c   = min(max(eg.x, 0), n - 1);
        float adj = __int_as_float(eg.y);

        uint4  ku = ldg_el_u4(&g_kh4[c * 16 + sub], pol);
        float2 ec = ldg_el_f2(&eig2[c * 16 + sub], pol);
        uint4  vu = ldg_el_u4(&vh4[c * 16 + sub], pol);

        // dot: 8 k-halfs + 2 eig comps per lane
        __half2 h0 = *reinterpret_cast<__half2*>(&ku.x);
        __half2 h1 = *reinterpret_cast<__half2*>(&ku.y);
        __half2 h2 = *reinterpret_cast<__half2*>(&ku.z);
        __half2 h3 = *reinterpret_cast<__half2*>(&ku.w);
        float2 k01 = __half22float2(h0);
        float2 k23 = __half22float2(h1);
        float2 k45 = __half22float2(h2);
        float2 k67 = __half22float2(h3);

        float part = fmaf(qa.x, k01.x,
                     fmaf(qa.y, k01.y,
                     fmaf(qa.z, k23.x,
                     fmaf(qa.w, k23.y,
                     fmaf(qb.x, k45.x,
                     fmaf(qb.y, k45.y,
                     fmaf(qb.z, k67.x,
                     fmaf(qb.w, k67.y,
                     fmaf(lerx, ec.x, lery * ec.y)))))))));
        // reduce within the 16-lane group (each group -> its own edge score)
        part += __shfl_xor_sync(FULLMASK, part, 1);
        part += __shfl_xor_sync(FULLMASK, part, 2);
        part += __shfl_xor_sync(FULLMASK, part, 4);
        part += __shfl_xor_sync(FULLMASK, part, 8);

        float s0 = part;
        float s1 = cpar * adj;
        if (grp && !hasB) { s0 = -INFINITY; s1 = -INFINITY; }  // kill dup tail

        float w0 = __expf(s0);               // 0 on killed tail
        float w1 = __expf(s1);
        z0 += w0; z1 += w1;

        // unpack my edge's 8 v-halfs and accumulate
        __half2 v0 = *reinterpret_cast<__half2*>(&vu.x);
        __half2 v1 = *reinterpret_cast<__half2*>(&vu.y);
        __half2 v2 = *reinterpret_cast<__half2*>(&vu.z);
        __half2 v3 = *reinterpret_cast<__half2*>(&vu.w);
        float2 f0 = __half22float2(v0);
        float2 f1 = __half22float2(v1);
        float2 f2 = __half22float2(v2);
        float2 f3 = __half22float2(v3);

        a0[0] = fmaf(w0, f0.x, a0[0]);  a1[0] = fmaf(w1, f0.x, a1[0]);
        a0[1] = fmaf(w0, f0.y, a0[1]);  a1[1] = fmaf(w1, f0.y, a1[1]);
        a0[2] = fmaf(w0, f1.x, a0[2]);  a1[2] = fmaf(w1, f1.x, a1[2]);
        a0[3] = fmaf(w0, f1.y, a0[3]);  a1[3] = fmaf(w1, f1.y, a1[3]);
        a0[4] = fmaf(w0, f2.x, a0[4]);  a1[4] = fmaf(w1, f2.x, a1[4]);
        a0[5] = fmaf(w0, f2.y, a0[5]);  a1[5] = fmaf(w1, f2.y, a1[5]);
        a0[6] = fmaf(w0, f3.x, a0[6]);  a1[6] = fmaf(w1, f3.x, a1[6]);
        a0[7] = fmaf(w0, f3.y, a0[7]);  a1[7] = fmaf(w1, f3.y, a1[7]);
    }

    // merge the two groups (once per row)
    z0 += __shfl_xor_sync(FULLMASK, z0, 16);
    z1 += __shfl_xor_sync(FULLMASK, z1, 16);
#pragma unroll
    for (int j = 0; j < 8; j++) {
        a0[j] += __shfl_xor_sync(FULLMASK, a0[j], 16);
        a1[j] += __shfl_xor_sync(FULLMASK, a1[j], 16);
    }

    float i0 = 0.5f / z0;
    float i1 = 0.5f / z1;
    int b = grp * 4;   // group A writes comps [8sub..+4), B writes [8sub+4..+8)
    float4 o;
    o.x = fmaf(a0[b + 0], i0, a1[b + 0] * i1);
    o.y = fmaf(a0[b + 1], i0, a1[b + 1] * i1);
    o.z = fmaf(a0[b + 2], i0, a1[b + 2] * i1);
    o.w = fmaf(a0[b + 3], i0, a1[b + 3] * i1);
    __stcs(&out4[oidx], o);
}

// ---------------------------------------------------------------------------
extern "C" void kernel_launch(void* const* d_in, const int* in_sizes, int n_in,
                              void* d_out, int out_size) {
    const float* q       = (const float*)d_in[0];
    const float* k       = (const float*)d_in[1];
    const float* v       = (const float*)d_in[2];
    const float* eigs    = (const float*)d_in[3];
    const float* adj     = (const float*)d_in[4];
    const float* lambda0 = (const float*)d_in[5];
    const float* gamma   = (const float*)d_in[6];
    const float* memb    = (const float*)d_in[7];
    const int*   row     = (const int*)d_in[8];
    const int*   col     = (const int*)d_in[9];
    const int*   mids    = (const int*)d_in[10];

    int n = in_sizes[10];  // N
    int e = in_sizes[8];   // E

    k_init<<<(n + 255) / 256, 256>>>(memb, mids, n);
    k_pack<<<2048, 256>>>((const float4*)k, (const float4*)v, n);
    k_hist<<<2048, 256>>>(row, e);
    k_scan_a<<<SCAN_BLOCKS, SCAN_THREADS>>>(n);
    k_scan_b<<<1, SCAN_BLOCKS>>>(n, e);
    k_scan_c<<<SCAN_BLOCKS, SCAN_THREADS>>>(n);
    k_scatter<<<2048, 256>>>(row, col, adj, e);
    k_par<<<1, 32>>>(lambda0, gamma);
    k_main<<<(n * 32 + 255) / 256, 256>>>(
        (const float4*)q, (const float2*)eigs, (float4*)d_out, n, e);
}

// round 17
// speedup vs baseline: 1.1356x; 1.0039x over previous
#include <cuda_runtime.h>
#include <cuda_fp16.h>
#include <math.h>

// Problem-fixed sizes: N=100000, E=1600000, D=128, EIG=32.
#define MAXN 100000
#define MAXE 1600000
#define FULLMASK 0xffffffffu
#define SCAN_BLOCKS 128
#define SCAN_THREADS 1024

// Scratch (device globals — zeroed/reset by k_init_pack every call).
__device__ float g_me[MAXN];
__device__ int   g_cnt[MAXN];
__device__ int   g_off[MAXN + 1];
__device__ float g_acc[3];
__device__ float g_par[2];           // [0]=exp(lambda0), [1]=c = gamma*sim
__device__ int2  g_edge[MAXE];       // (col, adj-as-int) sorted by row
__device__ uint4 g_vh4[MAXN * 16];   // v fp16: 8 halfs per uint4
__device__ uint4 g_kh4[MAXN * 16];   // k fp16: 8 halfs per uint4
__device__ unsigned g_eh[MAXN * 16]; // eigs fp16: 2 halfs per uint (col side)
__device__ int   g_bsum[SCAN_BLOCKS];
__device__ int   g_bbase[SCAN_BLOCKS];
__device__ int   g_done_a;           // ticket for scan_a last-block fold
__device__ int   g_done_s;           // ticket for scatter last-block fold

// ---- cache-policy-steered load helpers ----
__device__ __forceinline__ unsigned long long mk_policy_el() {
    unsigned long long pol;
    asm("createpolicy.fractional.L2::evict_last.b64 %0, 1.0;" : "=l"(pol));
    return pol;
}
__device__ __forceinline__ float2 ldg_el_f2(const float2* p,
                                            unsigned long long pol) {
    float2 r;
    asm("ld.global.nc.L2::cache_hint.v2.f32 {%0,%1},[%2],%3;"
        : "=f"(r.x), "=f"(r.y) : "l"(p), "l"(pol));
    return r;
}
__device__ __forceinline__ unsigned ldg_el_u1(const unsigned* p,
                                              unsigned long long pol) {
    unsigned r;
    asm("ld.global.nc.L2::cache_hint.u32 %0,[%1],%2;" : "=r"(r)
        : "l"(p), "l"(pol));
    return r;
}
__device__ __forceinline__ uint4 ldg_el_u4(const uint4* p,
                                           unsigned long long pol) {
    uint4 r;
    asm("ld.global.nc.L2::cache_hint.v4.u32 {%0,%1,%2,%3},[%4],%5;"
        : "=r"(r.x), "=r"(r.y), "=r"(r.z), "=r"(r.w) : "l"(p), "l"(pol));
    return r;
}

// ---------------------------------------------------------------------------
// K0: FUSED init + pack. Zeroes counters, computes me, packs k/v/eig to fp16.
// All pieces independent; one launch instead of two.
// ---------------------------------------------------------------------------
__global__ void k_init_pack(const float* __restrict__ memb,
                            const int* __restrict__ mids,
                            const float4* __restrict__ k4,
                            const float4* __restrict__ v4,
                            const float2* __restrict__ eig2, int n) {
    int stride = gridDim.x * blockDim.x;
    int t0 = blockIdx.x * blockDim.x + threadIdx.x;
    if (t0 == 0) {
        g_acc[0] = 0.f; g_acc[1] = 0.f; g_acc[2] = 0.f;
        g_done_a = 0;   g_done_s = 0;
    }
    for (int i = t0; i < n; i += stride) {
        g_me[i]  = memb[__ldcs(&mids[i])];
        g_cnt[i] = 0;
    }
    int n16 = n * 16;
    for (int i = t0; i < n16; i += stride) {
        float4 a = __ldcs(&k4[2 * i]);
        float4 b = __ldcs(&k4[2 * i + 1]);
        __half2 h0 = __floats2half2_rn(a.x, a.y);
        __half2 h1 = __floats2half2_rn(a.z, a.w);
        __half2 h2 = __floats2half2_rn(b.x, b.y);
        __half2 h3 = __floats2half2_rn(b.z, b.w);
        uint4 u;
        u.x = *reinterpret_cast<unsigned*>(&h0);
        u.y = *reinterpret_cast<unsigned*>(&h1);
        u.z = *reinterpret_cast<unsigned*>(&h2);
        u.w = *reinterpret_cast<unsigned*>(&h3);
        g_kh4[i] = u;

        float4 va = __ldcs(&v4[2 * i]);
        float4 vb = __ldcs(&v4[2 * i + 1]);
        __half2 g0 = __floats2half2_rn(va.x, va.y);
        __half2 g1 = __floats2half2_rn(va.z, va.w);
        __half2 g2 = __floats2half2_rn(vb.x, vb.y);
        __half2 g3 = __floats2half2_rn(vb.z, vb.w);
        uint4 w;
        w.x = *reinterpret_cast<unsigned*>(&g0);
        w.y = *reinterpret_cast<unsigned*>(&g1);
        w.z = *reinterpret_cast<unsigned*>(&g2);
        w.w = *reinterpret_cast<unsigned*>(&g3);
        g_vh4[i] = w;

        float2 ee = __ldcs(&eig2[i]);
        __half2 eh = __floats2half2_rn(ee.x, ee.y);
        g_eh[i] = *reinterpret_cast<unsigned*>(&eh);
    }
}

// ---------------------------------------------------------------------------
__global__ void k_hist(const int* __restrict__ row, int e) {
    for (int i = blockIdx.x * blockDim.x + threadIdx.x; i < e;
         i += gridDim.x * blockDim.x) {
        atomicAdd(&g_cnt[__ldcs(&row[i])], 1);
    }
}

// ---------------------------------------------------------------------------
// Scan stage A (+ folded stage B in the last-finishing block).
// ---------------------------------------------------------------------------
__global__ void k_scan_a(int n, int e) {
    __shared__ int wsum[32];
    __shared__ int ws[4];
    __shared__ int is_last;
    int t = threadIdx.x, lane = t & 31, warp = t >> 5;
    int i = blockIdx.x * SCAN_THREADS + t;
    int v = (i < n) ? g_cnt[i] : 0;
    int s = v;
#pragma unroll
    for (int o = 16; o; o >>= 1) s += __shfl_down_sync(FULLMASK, s, o);
    if (!lane) wsum[warp] = s;
    __syncthreads();
    if (warp == 0) {
        int x = wsum[lane];
#pragma unroll
        for (int o = 16; o; o >>= 1) x += __shfl_down_sync(FULLMASK, x, o);
        if (!lane) {
            g_bsum[blockIdx.x] = x;
            __threadfence();
            int tk = atomicAdd(&g_done_a, 1);
            is_last = (tk == SCAN_BLOCKS - 1);
        }
    }
    __syncthreads();
    if (is_last) {                      // folded scan_b, block-uniform branch
        __threadfence();                // make all g_bsum writes visible
        int bv = 0, inc = 0;
        if (t < SCAN_BLOCKS) {          // warps 0-3, warp-uniform guard
            bv = g_bsum[t];
            inc = bv;
#pragma unroll
            for (int o = 1; o < 32; o <<= 1) {
                int u = __shfl_up_sync(FULLMASK, inc, o);
                if (lane >= o) inc += u;
            }
            if (lane == 31) ws[warp] = inc;
        }
        __syncthreads();
        if (t == 0) {
            int run = 0;
            for (int j = 0; j < 4; j++) { int x = ws[j]; ws[j] = run; run += x; }
            g_off[n] = e;
            g_done_a = 0;               // reset for next call
        }
        __syncthreads();
        if (t < SCAN_BLOCKS) g_bbase[t] = ws[warp] + (inc - bv);
    }
}

// ---------------------------------------------------------------------------
__global__ void k_scan_c(int n) {
    __shared__ int wsum[32];
    int t = threadIdx.x, lane = t & 31, warp = t >> 5;
    int i = blockIdx.x * SCAN_THREADS + t;
    int v = (i < n) ? g_cnt[i] : 0;
    int inc = v;
#pragma unroll
    for (int o = 1; o < 32; o <<= 1) {
        int u = __shfl_up_sync(FULLMASK, inc, o);
        if (lane >= o) inc += u;
    }
    if (lane == 31) wsum[warp] = inc;
    __syncthreads();
    if (warp == 0) {
        int x = wsum[lane];
        int winc = x;
#pragma unroll
        for (int o = 1; o < 32; o <<= 1) {
            int u = __shfl_up_sync(FULLMASK, winc, o);
            if (lane >= o) winc += u;
        }
        wsum[lane] = winc - x;
    }
    __syncthreads();
    int run = g_bbase[blockIdx.x] + wsum[warp] + (inc - v);
    if (i < n) {
        g_off[i] = run;
        g_cnt[i] = run;
    }
}

// ---------------------------------------------------------------------------
// K3: counting-sort scatter + cosine-sim reduction (+ folded k_par in the
// last-finishing block).
// ---------------------------------------------------------------------------
__global__ void k_scatter(const int* __restrict__ row,
                          const int* __restrict__ col,
                          const float* __restrict__ adj,
                          const float* __restrict__ lambda0,
                          const float* __restrict__ gamma, int e) {
    float pab = 0.f, pa2 = 0.f, pb2 = 0.f;
    for (int i = blockIdx.x * blockDim.x + threadIdx.x; i < e;
         i += gridDim.x * blockDim.x) {
        int r = __ldcs(&row[i]), c = __ldcs(&col[i]);
        int pos = atomicAdd(&g_cnt[r], 1);
        pos = min(max(pos, 0), MAXE - 1);
        g_edge[pos] = make_int2(c, __float_as_int(__ldcs(&adj[i])));
        float a = g_me[r], b = g_me[c];
        pab = fmaf(a, b, pab);
        pa2 = fmaf(a, a, pa2);
        pb2 = fmaf(b, b, pb2);
    }
#pragma unroll
    for (int o = 16; o; o >>= 1) {
        pab += __shfl_down_sync(FULLMASK, pab, o);
        pa2 += __shfl_down_sync(FULLMASK, pa2, o);
        pb2 += __shfl_down_sync(FULLMASK, pb2, o);
    }
    __shared__ float sb[3][8];
    int w = threadIdx.x >> 5, l = threadIdx.x & 31;
    if (!l) { sb[0][w] = pab; sb[1][w] = pa2; sb[2][w] = pb2; }
    __syncthreads();
    if (!threadIdx.x) {
        float t0 = 0.f, t1 = 0.f, t2 = 0.f;
        int nw = blockDim.x >> 5;
        for (int j = 0; j < nw; j++) { t0 += sb[0][j]; t1 += sb[1][j]; t2 += sb[2][j]; }
        atomicAdd(&g_acc[0], t0);
        atomicAdd(&g_acc[1], t1);
        atomicAdd(&g_acc[2], t2);
        __threadfence();
        int tk = atomicAdd(&g_done_s, 1);
        if (tk == gridDim.x - 1) {      // folded k_par
            __threadfence();
            float sab = g_acc[0], sa2 = g_acc[1], sb2 = g_acc[2];
            float na = fmaxf(sqrtf(sa2), 1e-8f);
            float nb = fmaxf(sqrtf(sb2), 1e-8f);
            g_par[0] = expf(lambda0[0]);
            g_par[1] = gamma[0] * (sab / (na * nb));
            g_done_s = 0;               // reset for next call
        }
    }
}

// ---------------------------------------------------------------------------
// K4: SPLIT-GROUP dual-edge kernel (R16 winner) with eig gather in fp16
// (4B/lane instead of 8B — per-edge gather 640B -> 576B). Row-side eig
// stays fp32. Max-free softmax (scores bounded, |s|<~35<<88).
// ---------------------------------------------------------------------------
__global__ void __launch_bounds__(256)
k_main(const float4* __restrict__ q4, const float2* __restrict__ eig2,
       float4* __restrict__ out4, int n, int e) {
    int wid  = (blockIdx.x * blockDim.x + threadIdx.x) >> 5;
    int lane = threadIdx.x & 31;
    if (wid >= n) return;
    int start = g_off[wid];
    int end   = g_off[wid + 1];
    start = min(max(start, 0), e);
    end   = min(max(end, start), e);

    int sub  = lane & 15;
    int grp  = lane >> 4;                    // 0 = edge A, 1 = edge B
    int oidx = wid * 32 + 2 * sub + grp;     // this lane's output float4

    float4 zero = make_float4(0.f, 0.f, 0.f, 0.f);
    if (start == end) {
        out4[oidx] = zero;
        return;
    }
    unsigned long long pol = mk_policy_el();
    const float inv = 0.08838834764831845f;  // 1/sqrt(128)
    float cpar = g_par[1];
    float lam  = g_par[0];

    float4 qa = __ldcs(&q4[wid * 32 + 2 * sub]);
    float4 qb = __ldcs(&q4[wid * 32 + 2 * sub + 1]);
    qa.x *= inv; qa.y *= inv; qa.z *= inv; qa.w *= inv;
    qb.x *= inv; qb.y *= inv; qb.z *= inv; qb.w *= inv;
    float2 er = ldg_el_f2(&eig2[wid * 16 + sub], pol);   // row side fp32
    float lerx = lam * er.x, lery = lam * er.y;

    float z0 = 0.f, z1 = 0.f;
    float a0[8], a1[8];
#pragma unroll
    for (int j = 0; j < 8; j++) { a0[j] = 0.f; a1[j] = 0.f; }

    for (int i = start; i < end; i += 2) {
        bool hasB = (i + 1 < end);           // warp-uniform
        int  ei = i + grp;                   // my group's edge
        if (ei >= end) ei = i;               // tail: group B dups A (killed)
        int2 eg = g_edge[ei];                // 16-lane broadcast load
        int   c   = min(max(eg.x, 0), n - 1);
        float adj = __int_as_float(eg.y);

        uint4    ku  = ldg_el_u4(&g_kh4[c * 16 + sub], pol);
        unsigned ecu = ldg_el_u1(&g_eh[c * 16 + sub], pol);
        uint4    vu  = ldg_el_u4(&g_vh4[c * 16 + sub], pol);

        __half2 h0 = *reinterpret_cast<__half2*>(&ku.x);
        __half2 h1 = *reinterpret_cast<__half2*>(&ku.y);
        __half2 h2 = *reinterpret_cast<__half2*>(&ku.z);
        __half2 h3 = *reinterpret_cast<__half2*>(&ku.w);
        float2 k01 = __half22float2(h0);
        float2 k23 = __half22float2(h1);
        float2 k45 = __half22float2(h2);
        float2 k67 = __half22float2(h3);
        float2 ec  = __half22float2(*reinterpret_cast<__half2*>(&ecu));

        float part = fmaf(qa.x, k01.x,
                     fmaf(qa.y, k01.y,
                     fmaf(qa.z, k23.x,
                     fmaf(qa.w, k23.y,
                     fmaf(qb.x, k45.x,
                     fmaf(qb.y, k45.y,
                     fmaf(qb.z, k67.x,
                     fmaf(qb.w, k67.y,
                     fmaf(lerx, ec.x, lery * ec.y)))))))));
        part += __shfl_xor_sync(FULLMASK, part, 1);
        part += __shfl_xor_sync(FULLMASK, part, 2);
        part += __shfl_xor_sync(FULLMASK, part, 4);
        part += __shfl_xor_sync(FULLMASK, part, 8);

        float s0 = part;
        float s1 = cpar * adj;
        if (grp && !hasB) { s0 = -INFINITY; s1 = -INFINITY; }

        float w0 = __expf(s0);
        float w1 = __expf(s1);
        z0 += w0; z1 += w1;

        __half2 v0 = *reinterpret_cast<__half2*>(&vu.x);
        __half2 v1 = *reinterpret_cast<__half2*>(&vu.y);
        __half2 v2 = *reinterpret_cast<__half2*>(&vu.z);
        __half2 v3 = *reinterpret_cast<__half2*>(&vu.w);
        float2 f0 = __half22float2(v0);
        float2 f1 = __half22float2(v1);
        float2 f2 = __half22float2(v2);
        float2 f3 = __half22float2(v3);

        a0[0] = fmaf(w0, f0.x, a0[0]);  a1[0] = fmaf(w1, f0.x, a1[0]);
        a0[1] = fmaf(w0, f0.y, a0[1]);  a1[1] = fmaf(w1, f0.y, a1[1]);
        a0[2] = fmaf(w0, f1.x, a0[2]);  a1[2] = fmaf(w1, f1.x, a1[2]);
        a0[3] = fmaf(w0, f1.y, a0[3]);  a1[3] = fmaf(w1, f1.y, a1[3]);
        a0[4] = fmaf(w0, f2.x, a0[4]);  a1[4] = fmaf(w1, f2.x, a1[4]);
        a0[5] = fmaf(w0, f2.y, a0[5]);  a1[5] = fmaf(w1, f2.y, a1[5]);
        a0[6] = fmaf(w0, f3.x, a0[6]);  a1[6] = fmaf(w1, f3.x, a1[6]);
        a0[7] = fmaf(w0, f3.y, a0[7]);  a1[7] = fmaf(w1, f3.y, a1[7]);
    }

    // merge the two groups (once per row)
    z0 += __shfl_xor_sync(FULLMASK, z0, 16);
    z1 += __shfl_xor_sync(FULLMASK, z1, 16);
#pragma unroll
    for (int j = 0; j < 8; j++) {
        a0[j] += __shfl_xor_sync(FULLMASK, a0[j], 16);
        a1[j] += __shfl_xor_sync(FULLMASK, a1[j], 16);
    }

    float i0 = 0.5f / z0;
    float i1 = 0.5f / z1;
    int b = grp * 4;
    float4 o;
    o.x = fmaf(a0[b + 0], i0, a1[b + 0] * i1);
    o.y = fmaf(a0[b + 1], i0, a1[b + 1] * i1);
    o.z = fmaf(a0[b + 2], i0, a1[b + 2] * i1);
    o.w = fmaf(a0[b + 3], i0, a1[b + 3] * i1);
    __stcs(&out4[oidx], o);
}

// ---------------------------------------------------------------------------
extern "C" void kernel_launch(void* const* d_in, const int* in_sizes, int n_in,
                              void* d_out, int out_size) {
    const float* q       = (const float*)d_in[0];
    const float* k       = (const float*)d_in[1];
    const float* v       = (const float*)d_in[2];
    const float* eigs    = (const float*)d_in[3];
    const float* adj     = (const float*)d_in[4];
    const float* lambda0 = (const float*)d_in[5];
    const float* gamma   = (const float*)d_in[6];
    const float* memb    = (const float*)d_in[7];
    const int*   row     = (const int*)d_in[8];
    const int*   col     = (const int*)d_in[9];
    const int*   mids    = (const int*)d_in[10];

    int n = in_sizes[10];  // N
    int e = in_sizes[8];   // E

    k_init_pack<<<2048, 256>>>(memb, mids, (const float4*)k,
                               (const float4*)v, (const float2*)eigs, n);
    k_hist<<<2048, 256>>>(row, e);
    k_scan_a<<<SCAN_BLOCKS, SCAN_THREADS>>>(n, e);
    k_scan_c<<<SCAN_BLOCKS, SCAN_THREADS>>>(n);
    k_scatter<<<2048, 256>>>(row, col, adj, lambda0, gamma, e);
    k_main<<<(n * 32 + 255) / 256, 256>>>(
        (const float4*)q, (const float2*)eigs, (float4*)d_out, n, e);
}